// round 4
// baseline (speedup 1.0000x reference)
#include <cuda_runtime.h>

// Problem constants
#define BATCH    8
#define S_BYTES  8192
#define NUM_EMB  384
#define BYTE_DIM 128
#define EMB_DIM  1024
#define NUM_TOK  2048
#define SCALE_F  11.313708498984761f  // sqrt(128)

// proj = SCALE * emb @ W^T : [NUM_EMB, EMB_DIM] fp32 (1.5 MB, L2-resident)
__device__ float g_proj[NUM_EMB * EMB_DIM];
// Segment starts: g_start[b][t] = first byte index s with byte_groups[b][s] >= t
__device__ int g_start[BATCH][NUM_TOK + 1];

// ---------------------------------------------------------------------------
// Kernel 1 (fused): blocks [0,384) do the tiny GEMM proj = SCALE*emb@W^T,
// blocks [384,640) compute segment boundaries from sorted byte_groups.
// ---------------------------------------------------------------------------
#define BM 32
#define BN 32
#define SPITCH 33
#define GEMM_BLOCKS 384   // 12 x 32 tiles
#define SEG_BLOCKS  256   // 8 batches x 32 chunks

__global__ __launch_bounds__(256) void prep_kernel(const float* __restrict__ emb,
                                                   const float* __restrict__ W,
                                                   const int* __restrict__ bg) {
    const int tid = threadIdx.x;

    if (blockIdx.x >= GEMM_BLOCKS) {
        // ---- segment boundaries ----
        const int blkk = blockIdx.x - GEMM_BLOCKS;   // 0..255
        const int b    = blkk >> 5;                  // 0..7
        const int s    = (blkk & 31) * 256 + tid;    // 0..8191
        const int* __restrict__ row = bg + (size_t)b * S_BYTES;

        const int g  = row[s];
        const int gp = (s == 0) ? -1 : row[s - 1];
        for (int t = gp + 1; t <= g; ++t) g_start[b][t] = s;
        if (s == S_BYTES - 1) {
            for (int t = g + 1; t <= NUM_TOK; ++t) g_start[b][t] = S_BYTES;
        }
        return;
    }

    // ---- tiny GEMM: 32x32 tile, full K in smem ----
    __shared__ float As[BYTE_DIM][SPITCH];  // [k][m]
    __shared__ float Ws[BYTE_DIM][SPITCH];  // [k][n]

    const int bn = blockIdx.x & 31;   // 0..31
    const int bm = blockIdx.x >> 5;   // 0..11
    const int tx = tid & 15;
    const int ty = tid >> 4;
    const int m0 = ty * 2;
    const int n0 = tx * 2;

    const float* __restrict__ A  = emb + (size_t)(bm * BM) * BYTE_DIM;
    const float* __restrict__ Wt = W   + (size_t)(bn * BN) * BYTE_DIM;

    #pragma unroll
    for (int i = 0; i < 16; ++i) {
        int f = tid + i * 256;
        int k = f & 127;
        int r = f >> 7;
        As[k][r] = A [(size_t)r * BYTE_DIM + k];
        Ws[k][r] = Wt[(size_t)r * BYTE_DIM + k];
    }
    __syncthreads();

    float acc[2][2] = {};
    #pragma unroll 8
    for (int k = 0; k < BYTE_DIM; ++k) {
        float a0 = As[k][m0], a1 = As[k][m0 + 1];
        float w0 = Ws[k][n0], w1 = Ws[k][n0 + 1];
        acc[0][0] = fmaf(a0, w0, acc[0][0]);
        acc[0][1] = fmaf(a0, w1, acc[0][1]);
        acc[1][0] = fmaf(a1, w0, acc[1][0]);
        acc[1][1] = fmaf(a1, w1, acc[1][1]);
    }

    #pragma unroll
    for (int i = 0; i < 2; ++i) {
        float2 v = make_float2(acc[i][0] * SCALE_F, acc[i][1] * SCALE_F);
        *reinterpret_cast<float2*>(
            g_proj + (size_t)(bm * BM + m0 + i) * EMB_DIM + bn * BN + n0) = v;
    }
}

// ---------------------------------------------------------------------------
// Kernel 2: ragged mean with SMEM-staged proj slice.
// Grid (tok_split=4, ch_tile=8, batch=8) = 256 blocks, 512 threads.
// Each block stages proj[:, tile*128 .. +128) (192 KB) into dynamic smem,
// then each warp serves 32 tokens; lane owns one float4 (4 channels).
// Gather reads hit SMEM (36 TB/s aggregate) instead of L2 (12 TB/s cap).
// ---------------------------------------------------------------------------
#define TILE_F4   32               // 128 channels = 32 float4 per row
#define POOL_THREADS 512
#define TOK_SPLIT 4
#define TOK_PER_BLK (NUM_TOK / TOK_SPLIT)   // 512
#define TOK_PER_WARP (TOK_PER_BLK / 16)     // 32

__global__ __launch_bounds__(POOL_THREADS) void pool_kernel(const int* __restrict__ x,
                                                            float* __restrict__ out) {
    extern __shared__ float4 ps[];   // [NUM_EMB][TILE_F4] = 192 KB

    const int tsplit = blockIdx.x;   // 0..3
    const int tile   = blockIdx.y;   // 0..7
    const int b      = blockIdx.z;   // 0..7

    // Stage proj slice: 384 rows x 32 float4. proj row = 256 float4.
    const float4* __restrict__ gp = reinterpret_cast<const float4*>(g_proj);
    #pragma unroll
    for (int i = threadIdx.x; i < NUM_EMB * TILE_F4; i += POOL_THREADS) {
        int e = i >> 5;          // row
        int c = i & 31;          // col within tile
        ps[i] = gp[(size_t)e * (EMB_DIM / 4) + tile * TILE_F4 + c];
    }
    __syncthreads();

    const int wid  = threadIdx.x >> 5;
    const int lane = threadIdx.x & 31;
    const int* __restrict__ xr = x + (size_t)b * S_BYTES;
    float4* __restrict__ o = reinterpret_cast<float4*>(out);

    const int tbase = tsplit * TOK_PER_BLK + wid * TOK_PER_WARP;

    for (int i = 0; i < TOK_PER_WARP; ++i) {
        const int t  = tbase + i;
        const int s0 = g_start[b][t];
        const int s1 = g_start[b][t + 1];

        float4 acc = make_float4(0.f, 0.f, 0.f, 0.f);
        for (int s = s0; s < s1; ++s) {
            const int e = xr[s];                 // warp-broadcast (L1)
            float4 v = ps[e * TILE_F4 + lane];   // conflict-free SMEM
            acc.x += v.x; acc.y += v.y; acc.z += v.z; acc.w += v.w;
        }

        const int cnt = s1 - s0;
        const float inv = 1.0f / (float)(cnt > 0 ? cnt : 1);
        acc.x *= inv; acc.y *= inv; acc.z *= inv; acc.w *= inv;

        o[(((size_t)b * NUM_TOK) + t) * (EMB_DIM / 4) + tile * TILE_F4 + lane] = acc;
    }
}

// ---------------------------------------------------------------------------
// Launch
// ---------------------------------------------------------------------------
extern "C" void kernel_launch(void* const* d_in, const int* in_sizes, int n_in,
                              void* d_out, int out_size) {
    const int*   x    = (const int*)  d_in[0];  // [B, S_BYTES] int32
    const int*   bg   = (const int*)  d_in[1];  // [B, S_BYTES] int32 (sorted per row)
    const float* emb  = (const float*)d_in[2];  // [NUM_EMB, BYTE_DIM] fp32
    const float* wout = (const float*)d_in[3];  // [EMB_DIM, BYTE_DIM] fp32
    float* out = (float*)d_out;                 // [B, NUM_TOK, EMB_DIM] fp32

    (void)in_sizes; (void)n_in; (void)out_size;

    const int smem_bytes = NUM_EMB * TILE_F4 * sizeof(float4);  // 196608
    static bool attr_set = false;
    if (!attr_set) {
        cudaFuncSetAttribute(pool_kernel,
                             cudaFuncAttributeMaxDynamicSharedMemorySize, smem_bytes);
        attr_set = true;
    }

    prep_kernel<<<GEMM_BLOCKS + SEG_BLOCKS, 256>>>(emb, wout, bg);

    dim3 pgrid(TOK_SPLIT, EMB_DIM / (TILE_F4 * 4), BATCH);  // (4, 8, 8)
    pool_kernel<<<pgrid, POOL_THREADS, smem_bytes>>>(x, out);
}